// round 14
// baseline (speedup 1.0000x reference)
#include <cuda_runtime.h>
#include <math.h>

// Problem shape (fixed): B=256, T=1024, H=128, FUTURE=32.
#define BB    256
#define HH    128
#define KK1   129
#define KK2   257
#define KK3   385
#define NTHR  256          // 8 warps: 2 row-warps (4 rows each) x 4 k-sets
// 256 CTAs: 0..127 alpha (cell1+cell2, 8 rows), 128..255 beta (cell3+head)

// ---------------- device-global exchange state (allocation-free) -------------
__device__ __align__(16) float g_h1[2][HH * BB];
__device__ __align__(16) float g_h2[2][HH * BB];
__device__ __align__(16) float g_h3[2][HH * BB];
__device__ __align__(16) float g_ox[BB];
__device__ int g_flags[392 * 32];
// lines 0..127    : alpha(hg*8+bg)  -> 2t+1 after h1(t), 2t+2 after h2(t)
// lines 128..255  : beta intra      -> t+1 after h3(t) stored
// lines 256..383  : beta consumed   -> t+1 after staging h1(t),h2(t)
// lines 384..391  : o ready per bg  -> t+1 after o(t) in g_ox

__global__ void lstm_bar_init() {
    for (int i = threadIdx.x; i < 392 * 32; i += blockDim.x) g_flags[i] = 0;
}

// ---------------- flags ------------------------------------------------------
__device__ __forceinline__ void flag_set(int line, int val, int tid) {
    if (tid == 0) {
        __threadfence();
        asm volatile("st.relaxed.gpu.s32 [%0], %1;"
                     :: "l"(g_flags + line * 32), "r"(val) : "memory");
    }
}
__device__ __forceinline__ void flag_wait16(int base, int bg, int target, int tid) {
    if (tid < 16) {
        int v;
        const int *fp = g_flags + (base + tid * 8 + bg) * 32;
        do {
            asm volatile("ld.relaxed.gpu.s32 %0, [%1];" : "=r"(v) : "l"(fp) : "memory");
        } while (v < target);
    }
    __threadfence();
    __syncthreads();
}
__device__ __forceinline__ void flag_wait1(int line, int target, int tid) {
    if (tid == 0) {
        int v;
        const int *fp = g_flags + line * 32;
        do {
            asm volatile("ld.relaxed.gpu.s32 %0, [%1];" : "=r"(v) : "l"(fp) : "memory");
        } while (v < target);
    }
    __threadfence();
    __syncthreads();
}

// ---------------- f32x2 helpers ----------------------------------------------
__device__ __forceinline__ void ffma2(unsigned long long &d,
                                      unsigned long long a, unsigned long long b) {
    asm("fma.rn.f32x2 %0, %1, %2, %0;" : "+l"(d) : "l"(a), "l"(b));
}
__device__ __forceinline__ void addf2(unsigned long long &d, unsigned long long b) {
    asm("add.rn.f32x2 %0, %0, %1;" : "+l"(d) : "l"(b));
}
__device__ __forceinline__ float f2lo(unsigned long long v) {
    return __uint_as_float((unsigned)v);
}
__device__ __forceinline__ float f2hi(unsigned long long v) {
    return __uint_as_float((unsigned)(v >> 32));
}

// ---------------- activations (HW tanh) --------------------------------------
__device__ __forceinline__ float tanha(float x) {
    float r; asm("tanh.approx.f32 %0, %1;" : "=f"(r) : "f"(x)); return r;
}
__device__ __forceinline__ float sigf(float v) {
    return fmaf(0.5f, tanha(0.5f * v), 0.5f);
}
// one gate set, packed row-pair (lo=row0, hi=row1)
__device__ __forceinline__ void act_pair(unsigned long long gi, unsigned long long gf,
                                         unsigned long long gg, unsigned long long go,
                                         float &c0, float &c1, float &h0, float &h1) {
    float i0 = sigf(f2lo(gi)), i1 = sigf(f2hi(gi));
    float f0 = sigf(f2lo(gf)), f1 = sigf(f2hi(gf));
    float g0 = tanha(f2lo(gg)), g1 = tanha(f2hi(gg));
    float o0 = sigf(f2lo(go)), o1 = sigf(f2hi(go));
    c0 = f0 * c0 + i0 * g0;  c1 = f1 * c1 + i1 * g1;
    h0 = o0 * tanha(c0);     h1 = o1 * tanha(c1);
}

// ---------------- accumulation: 4 rows x 4 gates per thread, f32x2 -----------
// weights per k: 32 floats = [rw(2)][rp2(2)][g2(2)]{g-even (r0,r1), g-odd (r0,r1)}
struct Acc8 { unsigned long long a[8]; };   // [rp2*4 + gate]
__device__ __forceinline__ void zero8(Acc8 &A) {
#pragma unroll
    for (int j = 0; j < 8; j++) A.a[j] = 0ull;
}
__device__ __forceinline__ void load_bias(Acc8 &A, const float *biasc, int rw) {
    const ulonglong2 *bp = (const ulonglong2 *)biasc + rw * 4;
    ulonglong2 q0 = bp[0], q1 = bp[1], q2 = bp[2], q3 = bp[3];
    A.a[0] = q0.x; A.a[1] = q0.y; A.a[2] = q1.x; A.a[3] = q1.y;
    A.a[4] = q2.x; A.a[5] = q2.y; A.a[6] = q3.x; A.a[7] = q3.y;
}
template <int K0, int K1>
__device__ __forceinline__ void accum4(const ulonglong2 *__restrict__ W,
                                       Acc8 &A, const float *__restrict__ in_s,
                                       int lane, int rw) {
    const ulonglong2 *wp = W + rw * 4;
    const float *ip = in_s + lane;
#pragma unroll 2
    for (int k = K0; k < K1; k++) {
        ulonglong2 q0 = wp[k * 8 + 0];     // rp2=0, gates 0,1
        ulonglong2 q1 = wp[k * 8 + 1];     // rp2=0, gates 2,3
        ulonglong2 q2 = wp[k * 8 + 2];     // rp2=1, gates 0,1
        ulonglong2 q3 = wp[k * 8 + 3];     // rp2=1, gates 2,3
        float v = ip[k * 32];
        unsigned long long vv;
        asm("mov.b64 %0, {%1, %1};" : "=l"(vv) : "r"(__float_as_uint(v)));
        ffma2(A.a[0], q0.x, vv); ffma2(A.a[1], q0.y, vv);
        ffma2(A.a[2], q1.x, vv); ffma2(A.a[3], q1.y, vv);
        ffma2(A.a[4], q2.x, vv); ffma2(A.a[5], q2.y, vv);
        ffma2(A.a[6], q3.x, vv); ffma2(A.a[7], q3.y, vv);
    }
}
__device__ __forceinline__ void pub8(ulonglong2 *ps, int slot, const Acc8 &A) {
    ps[slot * 4 + 0] = make_ulonglong2(A.a[0], A.a[1]);
    ps[slot * 4 + 1] = make_ulonglong2(A.a[2], A.a[3]);
    ps[slot * 4 + 2] = make_ulonglong2(A.a[4], A.a[5]);
    ps[slot * 4 + 3] = make_ulonglong2(A.a[6], A.a[7]);
}
__device__ __forceinline__ void add8(Acc8 &A, const ulonglong2 *ps, int slot) {
#pragma unroll
    for (int j = 0; j < 4; j++) {
        ulonglong2 q = ps[slot * 4 + j];
        addf2(A.a[2 * j], q.x);
        addf2(A.a[2 * j + 1], q.y);
    }
}

// stage one h vector (32 cols, 128 rows) L2 -> smem slot, 256 threads
__device__ __forceinline__ void stage_h(const float *__restrict__ src,
                                        float *__restrict__ dst, int tid) {
    const float4 *s4 = (const float4 *)src;
    float4 *d4 = (float4 *)dst;
#pragma unroll
    for (int i = 0; i < 4; i++) {
        int idx = tid + i * NTHR;
        int row = idx >> 3, q = idx & 7;
        d4[row * 8 + q] = __ldcg(s4 + row * 64 + q);
    }
}

// ---------------- smem sizing (floats) ---------------------------------------
// alpha: ws1 4128 | ws2 8224 | bias 64 | big 8224 | psA 3072 (DEDICATED)
// beta : ws3 12320 | bias 32 | wl 388 | big 12320 | ps/po 1024 | ox 32
#define SMA_F (4128 + 8224 + 64 + 8224 + 3072 + 32)
#define SMB_F (12320 + 32 + 388 + 12320 + 1024 + 32 + 32)
#define SMEM_F (SMB_F > SMA_F ? SMB_F : SMA_F)
#define SMEM_BYTES (SMEM_F * 4)

__global__ void __launch_bounds__(NTHR, 2)
lstm_pipe_kernel(const float *__restrict__ x,
                 const float *__restrict__ Wi1, const float *__restrict__ Wh1,
                 const float *__restrict__ bi1, const float *__restrict__ bh1,
                 const float *__restrict__ Wi2, const float *__restrict__ Wh2,
                 const float *__restrict__ bi2, const float *__restrict__ bh2,
                 const float *__restrict__ Wi3, const float *__restrict__ Wh3,
                 const float *__restrict__ bi3, const float *__restrict__ bh3,
                 const float *__restrict__ Wl,  const float *__restrict__ bl,
                 float *__restrict__ out, int T, int NT) {
    extern __shared__ float sm[];
    const int tid  = threadIdx.x;
    const int lane = tid & 31;
    const int wid  = tid >> 5;          // 0..7
    const int rw   = wid & 1;           // row-warp: rows 4rw..4rw+3
    const int set  = wid >> 1;          // k-set 0..3

    if (blockIdx.x < 128) {
        // =================== alpha : cell1 + cell2 ===========================
        const int hg = blockIdx.x >> 3, bg = blockIdx.x & 7;
        const int line = hg * 8 + bg;
        const int bcol = bg * 32 + lane;

        float *ws1f  = sm;
        float *ws2f  = ws1f + 4128;
        float *biasf = ws2f + 8224;
        float *big   = biasf + 64;
        ulonglong2 *psA = (ulonglong2 *)(big + 8224);   // DEDICATED, no alias
        const ulonglong2 *W1 = (const ulonglong2 *)ws1f;
        const ulonglong2 *W2 = (const ulonglong2 *)ws2f;

        for (int idx = tid; idx < KK1 * 32; idx += NTHR) {
            int k = idx >> 5, t5 = idx & 31;
            int rww = t5 >> 4, rp2 = (t5 >> 3) & 1, g2 = (t5 >> 2) & 1, c = t5 & 3;
            int g = g2 * 2 + (c >> 1), rr = c & 1;
            int r = g * HH + hg * 8 + rww * 4 + rp2 * 2 + rr;
            ws1f[idx] = (k == 0) ? Wi1[r] : Wh1[r * HH + (k - 1)];
        }
        for (int idx = tid; idx < KK2 * 32; idx += NTHR) {
            int k = idx >> 5, t5 = idx & 31;
            int rww = t5 >> 4, rp2 = (t5 >> 3) & 1, g2 = (t5 >> 2) & 1, c = t5 & 3;
            int g = g2 * 2 + (c >> 1), rr = c & 1;
            int r = g * HH + hg * 8 + rww * 4 + rp2 * 2 + rr;
            ws2f[idx] = (k < KK1) ? Wi2[r * KK1 + k] : Wh2[r * HH + (k - KK1)];
        }
        if (tid < 64) {
            int cell = tid >> 5, t5 = tid & 31;
            int rww = t5 >> 4, rp2 = (t5 >> 3) & 1, g2 = (t5 >> 2) & 1, c = t5 & 3;
            int g = g2 * 2 + (c >> 1), rr = c & 1;
            int r = g * HH + hg * 8 + rww * 4 + rp2 * 2 + rr;
            biasf[tid] = cell ? (bi2[r] + bh2[r]) : (bi1[r] + bh1[r]);
        }
        for (int idx = tid; idx < KK2 * 32; idx += NTHR) big[idx] = 0.0f;
        __syncthreads();

        float c1s[4] = {0.f, 0.f, 0.f, 0.f};
        float c2s[4] = {0.f, 0.f, 0.f, 0.f};
        float xr = 0.f;
        if (tid < 32) xr = __ldg(&x[(bg * 32 + tid) * T]);

        for (int t = 0; t < NT; t++) {
            flag_wait16(256, bg, t - 1, tid);          // beta consumed (t-2)
            if (t >= T) {
                flag_wait1(384 + bg, t, tid);
                if (tid < 32) big[tid] = __ldcg(&g_ox[bg * 32 + tid]);
            } else {
                if (tid < 32) big[tid] = xr;
            }
            __syncthreads();

            // ---- cell 1 ------------------------------------------------------
            Acc8 A;
            if (set == 0) { load_bias(A, biasf, rw);      accum4<0, 33>(W1, A, big, lane, rw); }
            else if (set == 1) { zero8(A); accum4<33, 65>(W1, A, big, lane, rw); }
            else if (set == 2) { zero8(A); accum4<65, 97>(W1, A, big, lane, rw); }
            else               { zero8(A); accum4<97, 129>(W1, A, big, lane, rw); }
            if (set != 0) pub8(psA, (set - 1) * 64 + rw * 32 + lane, A);
            __syncthreads();
            if (set == 0) {
                add8(A, psA, rw * 32 + lane);
                add8(A, psA, 64 + rw * 32 + lane);
                add8(A, psA, 128 + rw * 32 + lane);
                float h0, h1, h2, h3;
                act_pair(A.a[0], A.a[1], A.a[2], A.a[3], c1s[0], c1s[1], h0, h1);
                act_pair(A.a[4], A.a[5], A.a[6], A.a[7], c1s[2], c1s[3], h2, h3);
                float *dst = g_h1[t & 1] + (hg * 8 + rw * 4) * BB + bcol;
                dst[0] = h0; dst[BB] = h1; dst[2 * BB] = h2; dst[3 * BB] = h3;
            }
            __syncthreads();
            flag_set(line, 2 * t + 1, tid);

            if (tid < 32 && t + 1 < T) xr = __ldg(&x[(bg * 32 + tid) * T + t + 1]);

            flag_wait16(0, bg, 2 * t, tid);            // nearly free
            if (t > 0) stage_h(&g_h2[(t - 1) & 1][bg * 32], big + 129 * 32, tid);
            __syncthreads();

            // ---- cell 2 partial: x + h2_prev ---------------------------------
            Acc8 B;
            if (set == 0) {
                load_bias(B, biasf + 32, rw);
                accum4<0, 1>(W2, B, big, lane, rw);
                accum4<129, 161>(W2, B, big, lane, rw);
            } else if (set == 1) { zero8(B); accum4<161, 193>(W2, B, big, lane, rw); }
            else if (set == 2)   { zero8(B); accum4<193, 225>(W2, B, big, lane, rw); }
            else                 { zero8(B); accum4<225, 257>(W2, B, big, lane, rw); }

            flag_wait16(0, bg, 2 * t + 1, tid);        // h1(t) from peers
            stage_h(&g_h1[t & 1][bg * 32], big + 32, tid);
            __syncthreads();

            // ---- cell 2 finish over h1_new -----------------------------------
            if (set == 0)      accum4<1, 33>(W2, B, big, lane, rw);
            else if (set == 1) accum4<33, 65>(W2, B, big, lane, rw);
            else if (set == 2) accum4<65, 97>(W2, B, big, lane, rw);
            else               accum4<97, 129>(W2, B, big, lane, rw);
            if (set != 0) pub8(psA, (set - 1) * 64 + rw * 32 + lane, B);
            __syncthreads();
            if (set == 0) {
                add8(B, psA, rw * 32 + lane);
                add8(B, psA, 64 + rw * 32 + lane);
                add8(B, psA, 128 + rw * 32 + lane);
                float h0, h1, h2, h3;
                act_pair(B.a[0], B.a[1], B.a[2], B.a[3], c2s[0], c2s[1], h0, h1);
                act_pair(B.a[4], B.a[5], B.a[6], B.a[7], c2s[2], c2s[3], h2, h3);
                float *dst = g_h2[t & 1] + (hg * 8 + rw * 4) * BB + bcol;
                dst[0] = h0; dst[BB] = h1; dst[2 * BB] = h2; dst[3 * BB] = h3;
            }
            __syncthreads();
            flag_set(line, 2 * t + 2, tid);
        }
    } else {
        // =================== beta : cell3 + head =============================
        const int bidx = blockIdx.x - 128;
        const int hg = bidx >> 3, bg = bidx & 7;
        const int bcol = bg * 32 + lane;
        const int sub = wid;

        float *ws3f  = sm;
        float *biasf = ws3f + 12320;
        float *wl    = biasf + 32;
        float *big   = wl + 388;
        float *po_s  = big + 12320;                     // union with psB (1024)
        ulonglong2 *psB = (ulonglong2 *)po_s;
        float *ox    = po_s + 1024;
        const ulonglong2 *W3 = (const ulonglong2 *)ws3f;

        for (int idx = tid; idx < KK3 * 32; idx += NTHR) {
            int k = idx >> 5, t5 = idx & 31;
            int rww = t5 >> 4, rp2 = (t5 >> 3) & 1, g2 = (t5 >> 2) & 1, c = t5 & 3;
            int g = g2 * 2 + (c >> 1), rr = c & 1;
            int r = g * HH + hg * 8 + rww * 4 + rp2 * 2 + rr;
            ws3f[idx] = (k < 257) ? Wi3[r * 257 + k] : Wh3[r * HH + (k - 257)];
        }
        if (tid < 32) {
            int t5 = tid;
            int rww = t5 >> 4, rp2 = (t5 >> 3) & 1, g2 = (t5 >> 2) & 1, c = t5 & 3;
            int g = g2 * 2 + (c >> 1), rr = c & 1;
            int r = g * HH + hg * 8 + rww * 4 + rp2 * 2 + rr;
            biasf[tid] = bi3[r] + bh3[r];
        }
        for (int idx = tid; idx < 385; idx += NTHR) wl[idx] = Wl[idx];
        if (tid == 0) wl[385] = bl[0];
        if (tid < 32) ox[tid] = 0.0f;
        for (int idx = tid; idx < KK3 * 32; idx += NTHR) big[idx] = 0.0f;
        __syncthreads();

        float c3s[4] = {0.f, 0.f, 0.f, 0.f};
        float xr = 0.f;
        if (tid < 32) xr = __ldg(&x[(bg * 32 + tid) * T]);

        for (int t = 0; t < NT; t++) {
            if (tid < 32) big[tid] = (t < T) ? xr : ox[tid];
            __syncthreads();

            // ---- cell3 partial: x + h3_prev ----------------------------------
            Acc8 D;
            if (set == 0) {
                load_bias(D, biasf, rw);
                accum4<0, 1>(W3, D, big, lane, rw);
                accum4<257, 289>(W3, D, big, lane, rw);
            } else if (set == 1) { zero8(D); accum4<289, 321>(W3, D, big, lane, rw); }
            else if (set == 2)   { zero8(D); accum4<321, 353>(W3, D, big, lane, rw); }
            else                 { zero8(D); accum4<353, 385>(W3, D, big, lane, rw); }

            flag_wait16(0, bg, 2 * t + 2, tid);        // alpha step t done
            stage_h(&g_h1[t & 1][bg * 32], big + 32, tid);
            stage_h(&g_h2[t & 1][bg * 32], big + 129 * 32, tid);
            __syncthreads();
            flag_set(256 + hg * 8 + bg, t + 1, tid);

            if (tid < 32 && t + 1 < T) xr = __ldg(&x[(bg * 32 + tid) * T + t + 1]);

            // ---- cell 3 finish over h1,h2 ------------------------------------
            if (set == 0)      accum4<1, 65>(W3, D, big, lane, rw);
            else if (set == 1) accum4<65, 129>(W3, D, big, lane, rw);
            else if (set == 2) accum4<129, 193>(W3, D, big, lane, rw);
            else               accum4<193, 257>(W3, D, big, lane, rw);

            // serialized 4-set combine in 4KB psB (disjoint from big)
            {
                int slot = rw * 32 + lane;
                if (set == 1) pub8(psB, slot, D);
                __syncthreads();
                if (set == 2) { add8(D, psB, slot); pub8(psB, slot, D); }
                __syncthreads();
                if (set == 3) { add8(D, psB, slot); pub8(psB, slot, D); }
                __syncthreads();
                if (set == 0) add8(D, psB, slot);
            }
            if (set == 0) {
                float h0, h1, h2, h3;
                act_pair(D.a[0], D.a[1], D.a[2], D.a[3], c3s[0], c3s[1], h0, h1);
                act_pair(D.a[4], D.a[5], D.a[6], D.a[7], c3s[2], c3s[3], h2, h3);
                float *dst = g_h3[t & 1] + (hg * 8 + rw * 4) * BB + bcol;
                dst[0] = h0; dst[BB] = h1; dst[2 * BB] = h2; dst[3 * BB] = h3;
            }
            __syncthreads();
            flag_set(128 + hg * 8 + bg, t + 1, tid);

            // head partial over x,h1,h2 while peers store h3
            float hp = 0.0f;
            for (int k = sub; k < 257; k += 8)
                hp = fmaf(wl[k], big[k * 32 + lane], hp);

            flag_wait16(128, bg, t + 1, tid);
            stage_h(&g_h3[t & 1][bg * 32], big + 257 * 32, tid);  // persists to t+1
            __syncthreads();

            for (int k = 257 + sub; k < 385; k += 8)
                hp = fmaf(wl[k], big[k * 32 + lane], hp);
            po_s[sub * 32 + lane] = hp;
            __syncthreads();
            if (tid < 32) {
                float o = wl[385];
#pragma unroll
                for (int s = 0; s < 8; s++) o += po_s[s * 32 + tid];
                ox[tid] = o;
                if (hg == 0) {
                    out[(bg * 32 + tid) * NT + t] = o;
                    g_ox[bg * 32 + tid] = o;
                }
            }
            __syncthreads();
            if (hg == 0) flag_set(384 + bg, t + 1, tid);
        }
    }
}

extern "C" void kernel_launch(void* const* d_in, const int* in_sizes, int n_in,
                              void* d_out, int out_size) {
    const float *x   = (const float *)d_in[0];
    const float *Wi1 = (const float *)d_in[1];
    const float *Wh1 = (const float *)d_in[2];
    const float *bi1 = (const float *)d_in[3];
    const float *bh1 = (const float *)d_in[4];
    const float *Wi2 = (const float *)d_in[5];
    const float *Wh2 = (const float *)d_in[6];
    const float *bi2 = (const float *)d_in[7];
    const float *bh2 = (const float *)d_in[8];
    const float *Wi3 = (const float *)d_in[9];
    const float *Wh3 = (const float *)d_in[10];
    const float *bi3 = (const float *)d_in[11];
    const float *bh3 = (const float *)d_in[12];
    const float *Wl  = (const float *)d_in[13];
    const float *bl  = (const float *)d_in[14];
    float *out = (float *)d_out;

    int T  = in_sizes[0] / BB;   // 1024
    int NT = out_size / BB;      // 1056

    cudaFuncSetAttribute(lstm_pipe_kernel,
                         cudaFuncAttributeMaxDynamicSharedMemorySize, SMEM_BYTES);

    lstm_bar_init<<<1, 256>>>();
    lstm_pipe_kernel<<<256, NTHR, SMEM_BYTES>>>(
        x, Wi1, Wh1, bi1, bh1, Wi2, Wh2, bi2, bh2,
        Wi3, Wh3, bi3, bh3, Wl, bl, out, T, NT);
}